// round 15
// baseline (speedup 1.0000x reference)
#include <cuda_runtime.h>
#include <cuda_fp16.h>

#define HH 128
#define WW 128
#define CC 512
#define HWSZ (HH*WW)
#define NANCH 12

#define LOC_OFF   0
#define CLS_OFF   786432
#define ROI_OFF   1179648

// ---------------------------------------------------------------------------
// Global scratch (allocation-free)
// ---------------------------------------------------------------------------
__device__ __align__(256) __half g_xhi[HWSZ * CC];        // x NHWC fp16
__device__ __align__(256) __half g_wh [9 * CC * CC];      // conv W [tap][oc][ic]
__device__ __align__(256) __half g_part[4][HWSZ * CC];    // K-split partials fp16
__device__ __align__(256) __half g_mhi[HWSZ * CC];        // mid NHWC hi
__device__ __align__(256) __half g_mlo[HWSZ * CC];        // mid NHWC lo
__device__ __align__(256) __half g_hw [8 * 72 * 64];      // head W [kc][row72][64]

// ---------------------------------------------------------------------------
// Helpers (plain sm_80+ PTX, legal on the non-'a' compute_103 target)
// ---------------------------------------------------------------------------
__device__ __forceinline__ unsigned smem_u32(const void* p){
    unsigned a;
    asm("{ .reg .u64 t; cvta.to.shared.u64 t, %1; cvt.u32.u64 %0, t; }" : "=r"(a) : "l"(p));
    return a;
}
#define SWZ(b) ((unsigned)(b) ^ ((((unsigned)(b)) >> 3) & 0x70u))

__device__ __forceinline__ void cp16(unsigned dst, const void* src, unsigned sz){
    asm volatile("cp.async.cg.shared.global [%0], [%1], 16, %2;"
        :: "r"(dst), "l"(src), "r"(sz) : "memory");
}
#define CP_COMMIT() asm volatile("cp.async.commit_group;" ::: "memory")
#define CP_WAIT(n)  asm volatile("cp.async.wait_group %0;" :: "n"(n) : "memory")

__device__ __forceinline__ void ldm4(unsigned* r, unsigned addr){
    asm volatile("ldmatrix.sync.aligned.m8n8.x4.shared.b16 {%0,%1,%2,%3}, [%4];"
        : "=r"(r[0]), "=r"(r[1]), "=r"(r[2]), "=r"(r[3]) : "r"(addr));
}
__device__ __forceinline__ void ldm2(unsigned* r, unsigned addr){
    asm volatile("ldmatrix.sync.aligned.m8n8.x2.shared.b16 {%0,%1}, [%2];"
        : "=r"(r[0]), "=r"(r[1]) : "r"(addr));
}
__device__ __forceinline__ void mma16816(float* d, const unsigned* a, const unsigned* b){
    asm volatile("mma.sync.aligned.m16n8k16.row.col.f32.f16.f16.f32 "
        "{%0,%1,%2,%3}, {%4,%5,%6,%7}, {%8,%9}, {%0,%1,%2,%3};"
        : "+f"(d[0]), "+f"(d[1]), "+f"(d[2]), "+f"(d[3])
        : "r"(a[0]), "r"(a[1]), "r"(a[2]), "r"(a[3]), "r"(b[0]), "r"(b[1]));
}

// ---------------------------------------------------------------------------
// Prep kernels
// ---------------------------------------------------------------------------
__global__ void prep_x_kernel(const float* __restrict__ x){
    __shared__ float tile[32][33];
    int hw0 = blockIdx.x * 32, c0 = blockIdx.y * 32;
    int tx = threadIdx.x, ty = threadIdx.y;
    #pragma unroll
    for (int i = 0; i < 32; i += 8)
        tile[ty + i][tx] = x[(size_t)(c0 + ty + i) * HWSZ + hw0 + tx];
    __syncthreads();
    #pragma unroll
    for (int i = 0; i < 32; i += 8){
        int hw = ty + i;
        g_xhi[(size_t)(hw0 + hw) * CC + c0 + tx] = __float2half(tile[tx][hw]);
    }
}

// prep_w: block = one oc, coalesced read + transposed coalesced writes
__global__ void __launch_bounds__(256) prep_w_kernel(const float* __restrict__ w){
    __shared__ float buf[4608];
    const int oc = blockIdx.x;
    const int tid = threadIdx.x;
    const float* src = w + (size_t)oc * 4608;
    #pragma unroll
    for (int j = 0; j < 18; j++)
        buf[tid + j * 256] = src[tid + j * 256];
    __syncthreads();
    #pragma unroll
    for (int tap = 0; tap < 9; tap++){
        __half* dst = g_wh + (size_t)tap * (CC * CC) + (size_t)oc * CC;
        dst[tid]       = __float2half(buf[tid * 9 + tap]);
        dst[tid + 256] = __float2half(buf[(tid + 256) * 9 + tap]);
    }
}

__global__ void prep_hw_kernel(const float* __restrict__ loc_w,
                               const float* __restrict__ score_w){
    int idx = blockIdx.x * 256 + threadIdx.x;
    if (idx >= 8 * 72 * 64) return;
    int kc  = idx / (72 * 64);
    int rem = idx % (72 * 64);
    int row = rem >> 6;
    int k   = rem & 63;
    float v = (row < 48) ? loc_w[row * CC + kc * 64 + k]
                         : score_w[(row - 48) * CC + kc * 64 + k];
    g_hw[idx] = __float2half(v);
}

// ---------------------------------------------------------------------------
// Conv 3x3, single-pass fp16, K-split x4.
// grid (64 row-pairs, 4 ocg, 4 ks) = 1024 CTAs, 512 threads, 1 CTA/SM.
// CTA tile: M=256 x N=128, 18 chunks of 64 ic.
// 16 warps as 4 m-groups (64 rows) x 4 n-groups (32 oc); warp tile 64x32.
// Stage = A 32KB + B 16KB = 48KB; 3 stages (144KB), depth-2 prefetch,
// single __syncthreads per chunk (ring: refill stage (i+2)%3 held chunk
// i-1, proven finished by the barrier at top of iter i).
// Partials stored as fp16.
// ---------------------------------------------------------------------------
#define CSTG  49152
#define CDYN  (3*CSTG)

__device__ __forceinline__ void conv_load_chunk(unsigned sb, int ci, int s,
                                                int y2, int oc0, int tid){
    const int tap = ci >> 3;
    const int ic0 = (ci & 7) << 6;
    const int dy = tap / 3 - 1, dx = tap % 3 - 1;
    const unsigned stg = sb + s * CSTG;
    #pragma unroll
    for (int j = 0; j < 6; j++){
        int id = tid + j * 512;
        if (id < 2048){                       // A (32KB: 256 rows x 128B)
            int row = id >> 3, c = id & 7;
            unsigned dst = stg + SWZ(row * 128 + c * 16);
            int yr = 2 * y2 + (row >> 7) + dy;
            int xr = (row & 127) + dx;
            bool ok = ((unsigned)yr < 128u) && ((unsigned)xr < 128u);
            const __half* src = g_xhi +
                (ok ? ((size_t)(yr * 128 + xr) * CC + ic0 + c * 8) : 0);
            cp16(dst, src, ok ? 16u : 0u);
        } else {                              // B (16KB: 128 rows x 128B)
            int idb = id - 2048;
            int row = idb >> 3, c = idb & 7;
            unsigned dst = stg + 32768 + SWZ(row * 128 + c * 16);
            cp16(dst, g_wh + (size_t)tap * (CC * CC)
                     + (size_t)(oc0 + row) * CC + ic0 + c * 8, 16u);
        }
    }
}

__global__ void __launch_bounds__(512, 1) conv_mma_kernel(){
    extern __shared__ __align__(1024) char dsm[];
    const unsigned sb = smem_u32(dsm);
    const int tid = threadIdx.x, lane = tid & 31, wid = tid >> 5;
    const int y2 = blockIdx.x, oc0 = blockIdx.y * 128, ks = blockIdx.z;
    const int cbase = ks * 18;
    const int m0 = (wid & 3) * 64;            // 4 m-groups of 64 rows
    const int n0 = (wid >> 2) * 32;           // 4 n-groups of 32 oc

    float acc[4][4][4];
    #pragma unroll
    for (int a = 0; a < 4; a++)
        #pragma unroll
        for (int b = 0; b < 4; b++)
            #pragma unroll
            for (int c = 0; c < 4; c++) acc[a][b][c] = 0.f;

    const int a_row = lane & 15;
    const int a_kad = (lane >> 4) << 4;
    const int b_row = ((lane >> 4) << 3) + (lane & 7);
    const int b_kad = ((lane >> 3) & 1) << 4;

    conv_load_chunk(sb, cbase + 0, 0, y2, oc0, tid); CP_COMMIT();
    conv_load_chunk(sb, cbase + 1, 1, y2, oc0, tid); CP_COMMIT();

    int s = 0;
    for (int i = 0; i < 18; i++){
        if (i <= 16) CP_WAIT(1);
        else         CP_WAIT(0);
        __syncthreads();

        const unsigned Ah = sb + s * CSTG;
        const unsigned Bh = Ah + 32768;

        #pragma unroll
        for (int k16 = 0; k16 < 4; k16++){
            const int koff = k16 * 32;
            unsigned ah[4][4];
            #pragma unroll
            for (int mt = 0; mt < 4; mt++)
                ldm4(ah[mt], Ah + SWZ((m0 + mt * 16 + a_row) * 128 + koff + a_kad));
            unsigned bh[2][4];
            #pragma unroll
            for (int bt = 0; bt < 2; bt++)
                ldm4(bh[bt], Bh + SWZ((n0 + bt * 16 + b_row) * 128 + koff + b_kad));
            #pragma unroll
            for (int mt = 0; mt < 4; mt++)
                #pragma unroll
                for (int bt = 0; bt < 2; bt++){
                    mma16816(acc[mt][2*bt],   ah[mt], &bh[bt][0]);
                    mma16816(acc[mt][2*bt+1], ah[mt], &bh[bt][2]);
                }
        }

        if (i + 2 < 18){
            conv_load_chunk(sb, cbase + i + 2, (i + 2) % 3, y2, oc0, tid);
            CP_COMMIT();
        }
        s = (s == 2) ? 0 : s + 1;
    }

    // Store fp16 partials
    __half* pb = g_part[ks];
    const int er = lane >> 2;
    const int ec = (lane & 3) * 2;
    #pragma unroll
    for (int mt = 0; mt < 4; mt++){
        #pragma unroll
        for (int nt = 0; nt < 4; nt++){
            const int oc = oc0 + n0 + nt * 8 + ec;
            #pragma unroll
            for (int h = 0; h < 2; h++){
                const size_t p = (size_t)y2 * 256 + m0 + mt * 16 + er + h * 8;
                *(__half2*)&pb[p * CC + oc] =
                    __floats2half2_rn(acc[mt][nt][2*h+0], acc[mt][nt][2*h+1]);
            }
        }
    }
}

// ---------------------------------------------------------------------------
// Epilogue: sum 4 fp16 partials + bias + relu, split fp16 hi/lo
// ---------------------------------------------------------------------------
__global__ void __launch_bounds__(256) mid_epilogue_kernel(const float* __restrict__ bias){
    const size_t i4 = ((size_t)blockIdx.x * 256 + threadIdx.x) * 4;
    const int oc = (int)(i4 & 511);
    float4 b4 = *(const float4*)&bias[oc];
    float v[4] = {b4.x, b4.y, b4.z, b4.w};
    #pragma unroll
    for (int k = 0; k < 4; k++){
        uint2 raw = *(const uint2*)&g_part[k][i4];
        __half2 p01 = *reinterpret_cast<__half2*>(&raw.x);
        __half2 p23 = *reinterpret_cast<__half2*>(&raw.y);
        float2 f01 = __half22float2(p01);
        float2 f23 = __half22float2(p23);
        v[0] += f01.x; v[1] += f01.y; v[2] += f23.x; v[3] += f23.y;
    }
    #pragma unroll
    for (int k = 0; k < 4; k++) v[k] = fmaxf(v[k], 0.f);
    __half h0 = __float2half(v[0]), h1 = __float2half(v[1]);
    __half h2 = __float2half(v[2]), h3 = __float2half(v[3]);
    __half l0 = __float2half(v[0] - __half2float(h0));
    __half l1 = __float2half(v[1] - __half2float(h1));
    __half l2 = __float2half(v[2] - __half2float(h2));
    __half l3 = __float2half(v[3] - __half2float(h3));
    uint2 hp = make_uint2((unsigned)*(unsigned short*)&h0 | ((unsigned)*(unsigned short*)&h1 << 16),
                          (unsigned)*(unsigned short*)&h2 | ((unsigned)*(unsigned short*)&h3 << 16));
    uint2 lp = make_uint2((unsigned)*(unsigned short*)&l0 | ((unsigned)*(unsigned short*)&l1 << 16),
                          (unsigned)*(unsigned short*)&l2 | ((unsigned)*(unsigned short*)&l3 << 16));
    *(uint2*)&g_mhi[i4] = hp;
    *(uint2*)&g_mlo[i4] = lp;
}

// ---------------------------------------------------------------------------
// Head GEMM + fused roi decode. M=128/CTA (grid 128), N=72, K=512.
// ---------------------------------------------------------------------------
#define HB    73728
#define HASTG 32768
#define HDYN  (HB + 2*HASTG)

__device__ __forceinline__ void head_load_A(unsigned sb, int i, int s,
                                            int p0, int tid){
    const unsigned ast = sb + HB + s * HASTG;
    const int ic0 = i * 64;
    #pragma unroll
    for (int j = 0; j < 8; j++){
        int id = tid + j * 256;
        int part = id >> 10, rem = id & 1023;
        int row = rem >> 3, c = rem & 7;
        unsigned dst = ast + part * 16384 + SWZ(row * 128 + c * 16);
        const __half* base = part ? g_mlo : g_mhi;
        cp16(dst, base + (size_t)(p0 + row) * CC + ic0 + c * 8, 16u);
    }
}

__device__ __forceinline__ void emit_locroi(float* __restrict__ out,
                                            int p, int col, float v0, float v1){
    *(float2*)&out[LOC_OFF + (size_t)p * 48 + col] = make_float2(v0, v1);
    const int a = col >> 2;
    const float RAT[3] = {0.5f, 1.0f, 2.0f};
    const float SIZ[4] = {64.f, 128.f, 256.f, 512.f};
    float r = RAT[a >> 2], sz = SIZ[a & 3];
    float hr = sqrtf(r);
    float aw = rintf(0.5f * ((1.0f / hr) * sz));
    float ah = rintf(0.5f * (hr * sz));
    float gx = (float)((p >> 7) * 16);
    float gy = (float)((p & 127) * 16);
    float2 ro;
    if ((col & 3) == 0){
        ro = make_float2(v0 * aw + gx, v1 * ah + gy);
    } else {
        ro = make_float2(expf(v0) * aw, expf(v1) * ah);
    }
    *(float2*)&out[ROI_OFF + (size_t)p * 48 + col] = ro;
}

__global__ void __launch_bounds__(256, 1) head_mma_kernel(
        const float* __restrict__ loc_b, const float* __restrict__ score_b,
        float* __restrict__ out){
    extern __shared__ __align__(1024) char dsm[];
    const unsigned sb = smem_u32(dsm);
    const int tid = threadIdx.x, lane = tid & 31, wid = tid >> 5;
    const int p0 = blockIdx.x * 128;
    const int m0 = wid * 16;

    float acc[9][4];
    #pragma unroll
    for (int n = 0; n < 9; n++)
        #pragma unroll
        for (int c = 0; c < 4; c++) acc[n][c] = 0.f;

    #pragma unroll
    for (int j = 0; j < 18; j++){
        int id = tid + j * 256;
        int kc  = id / 576;
        int rem = id % 576;
        int row = rem >> 3, c = rem & 7;
        unsigned dst = sb + kc * 9216 + SWZ(row * 128 + c * 16);
        cp16(dst, g_hw + kc * 4608 + row * 64 + c * 8, 16u);
    }
    head_load_A(sb, 0, 0, p0, tid);
    CP_COMMIT();

    const int a_row = lane & 15;
    const int a_kad = (lane >> 4) << 4;
    const int b_row = lane & 7;
    const int b_kad = ((lane >> 3) & 1) << 4;

    for (int i = 0; i < 8; i++){
        const int s = i & 1;
        if (i < 7){
            head_load_A(sb, i + 1, (i + 1) & 1, p0, tid);
            CP_COMMIT();
            CP_WAIT(1);
        } else {
            CP_WAIT(0);
        }
        __syncthreads();

        const unsigned Ah = sb + HB + s * HASTG;
        const unsigned Al = Ah + 16384;
        const unsigned Bh = sb + i * 9216;

        #pragma unroll
        for (int k16 = 0; k16 < 4; k16++){
            const int koff = k16 * 32;
            unsigned ah[4], al[4];
            {
                unsigned off = SWZ((m0 + a_row) * 128 + koff + a_kad);
                ldm4(ah, Ah + off);
                ldm4(al, Al + off);
            }
            #pragma unroll
            for (int nt = 0; nt < 9; nt++){
                unsigned off = SWZ((nt * 8 + b_row) * 128 + koff + b_kad);
                unsigned bh2[2];
                ldm2(bh2, Bh + off);
                mma16816(acc[nt], ah, bh2);
                mma16816(acc[nt], al, bh2);
            }
        }
        __syncthreads();
    }

    const int er = lane >> 2;
    const int ec = (lane & 3) * 2;
    #pragma unroll
    for (int nt = 0; nt < 9; nt++){
        const int col = nt * 8 + ec;
        const int p1 = p0 + m0 + er;
        const int p2 = p1 + 8;
        if (col < 48){
            float2 b2 = *(const float2*)&loc_b[col];
            emit_locroi(out, p1, col, acc[nt][0] + b2.x, acc[nt][1] + b2.y);
            emit_locroi(out, p2, col, acc[nt][2] + b2.x, acc[nt][3] + b2.y);
        } else {
            const int cc2 = col - 48;
            float2 b2 = *(const float2*)&score_b[cc2];
            *(float2*)&out[CLS_OFF + (size_t)p1 * 24 + cc2] =
                make_float2(acc[nt][0] + b2.x, acc[nt][1] + b2.y);
            *(float2*)&out[CLS_OFF + (size_t)p2 * 24 + cc2] =
                make_float2(acc[nt][2] + b2.x, acc[nt][3] + b2.y);
        }
    }
}

// ---------------------------------------------------------------------------
extern "C" void kernel_launch(void* const* d_in, const int* in_sizes, int n_in,
                              void* d_out, int out_size){
    const float* x       = (const float*)d_in[0];
    const float* conv1_w = (const float*)d_in[1];
    const float* conv1_b = (const float*)d_in[2];
    const float* score_w = (const float*)d_in[3];
    const float* score_b = (const float*)d_in[4];
    const float* loc_w   = (const float*)d_in[5];
    const float* loc_b   = (const float*)d_in[6];
    float* out = (float*)d_out;

    cudaFuncSetAttribute(conv_mma_kernel,
        cudaFuncAttributeMaxDynamicSharedMemorySize, CDYN);
    cudaFuncSetAttribute(head_mma_kernel,
        cudaFuncAttributeMaxDynamicSharedMemorySize, HDYN);

    prep_x_kernel<<<dim3(HWSZ / 32, CC / 32), dim3(32, 8)>>>(x);
    prep_w_kernel<<<512, 256>>>(conv1_w);
    prep_hw_kernel<<<(8 * 72 * 64 + 255) / 256, 256>>>(loc_w, score_w);

    conv_mma_kernel<<<dim3(64, 4, 4), 512, CDYN>>>();

    mid_epilogue_kernel<<<(HWSZ * CC / 4) / 256, 256>>>(conv1_b);

    head_mma_kernel<<<128, 256, HDYN>>>(loc_b, score_b, out);
}

// round 16
// speedup vs baseline: 1.0654x; 1.0654x over previous
#include <cuda_runtime.h>
#include <cuda_fp16.h>

#define HH 128
#define WW 128
#define CC 512
#define HWSZ (HH*WW)
#define NANCH 12

#define LOC_OFF   0
#define CLS_OFF   786432
#define ROI_OFF   1179648

// ---------------------------------------------------------------------------
// Global scratch (allocation-free)
// ---------------------------------------------------------------------------
__device__ __align__(256) __half g_xhi[HWSZ * CC];        // x NHWC fp16
__device__ __align__(256) __half g_wh [9 * CC * CC];      // conv W [tap][oc][ic]
__device__ __align__(256) __half g_part[4][HWSZ * CC];    // K-split partials fp16
__device__ __align__(256) __half g_mhi[HWSZ * CC];        // mid NHWC hi
__device__ __align__(256) __half g_mlo[HWSZ * CC];        // mid NHWC lo
__device__ __align__(256) __half g_hw [8 * 72 * 64];      // head W [kc][row72][64]

// ---------------------------------------------------------------------------
// Helpers (plain sm_80+ PTX, legal on the non-'a' compute_103 target)
// ---------------------------------------------------------------------------
__device__ __forceinline__ unsigned smem_u32(const void* p){
    unsigned a;
    asm("{ .reg .u64 t; cvta.to.shared.u64 t, %1; cvt.u32.u64 %0, t; }" : "=r"(a) : "l"(p));
    return a;
}
#define SWZ(b) ((unsigned)(b) ^ ((((unsigned)(b)) >> 3) & 0x70u))

__device__ __forceinline__ void cp16(unsigned dst, const void* src, unsigned sz){
    asm volatile("cp.async.cg.shared.global [%0], [%1], 16, %2;"
        :: "r"(dst), "l"(src), "r"(sz) : "memory");
}
#define CP_COMMIT() asm volatile("cp.async.commit_group;" ::: "memory")
#define CP_WAIT(n)  asm volatile("cp.async.wait_group %0;" :: "n"(n) : "memory")

__device__ __forceinline__ void ldm4(unsigned* r, unsigned addr){
    asm volatile("ldmatrix.sync.aligned.m8n8.x4.shared.b16 {%0,%1,%2,%3}, [%4];"
        : "=r"(r[0]), "=r"(r[1]), "=r"(r[2]), "=r"(r[3]) : "r"(addr));
}
__device__ __forceinline__ void ldm2(unsigned* r, unsigned addr){
    asm volatile("ldmatrix.sync.aligned.m8n8.x2.shared.b16 {%0,%1}, [%2];"
        : "=r"(r[0]), "=r"(r[1]) : "r"(addr));
}
__device__ __forceinline__ void mma16816(float* d, const unsigned* a, const unsigned* b){
    asm volatile("mma.sync.aligned.m16n8k16.row.col.f32.f16.f16.f32 "
        "{%0,%1,%2,%3}, {%4,%5,%6,%7}, {%8,%9}, {%0,%1,%2,%3};"
        : "+f"(d[0]), "+f"(d[1]), "+f"(d[2]), "+f"(d[3])
        : "r"(a[0]), "r"(a[1]), "r"(a[2]), "r"(a[3]), "r"(b[0]), "r"(b[1]));
}

// ---------------------------------------------------------------------------
// Prep kernels
// ---------------------------------------------------------------------------
__global__ void prep_x_kernel(const float* __restrict__ x){
    __shared__ float tile[32][33];
    int hw0 = blockIdx.x * 32, c0 = blockIdx.y * 32;
    int tx = threadIdx.x, ty = threadIdx.y;
    #pragma unroll
    for (int i = 0; i < 32; i += 8)
        tile[ty + i][tx] = x[(size_t)(c0 + ty + i) * HWSZ + hw0 + tx];
    __syncthreads();
    #pragma unroll
    for (int i = 0; i < 32; i += 8){
        int hw = ty + i;
        g_xhi[(size_t)(hw0 + hw) * CC + c0 + tx] = __float2half(tile[tx][hw]);
    }
}

// prep_w: block = one oc, coalesced read + transposed coalesced writes
__global__ void __launch_bounds__(256) prep_w_kernel(const float* __restrict__ w){
    __shared__ float buf[4608];
    const int oc = blockIdx.x;
    const int tid = threadIdx.x;
    const float* src = w + (size_t)oc * 4608;
    #pragma unroll
    for (int j = 0; j < 18; j++)
        buf[tid + j * 256] = src[tid + j * 256];
    __syncthreads();
    #pragma unroll
    for (int tap = 0; tap < 9; tap++){
        __half* dst = g_wh + (size_t)tap * (CC * CC) + (size_t)oc * CC;
        dst[tid]       = __float2half(buf[tid * 9 + tap]);
        dst[tid + 256] = __float2half(buf[(tid + 256) * 9 + tap]);
    }
}

__global__ void prep_hw_kernel(const float* __restrict__ loc_w,
                               const float* __restrict__ score_w){
    int idx = blockIdx.x * 256 + threadIdx.x;
    if (idx >= 8 * 72 * 64) return;
    int kc  = idx / (72 * 64);
    int rem = idx % (72 * 64);
    int row = rem >> 6;
    int k   = rem & 63;
    float v = (row < 48) ? loc_w[row * CC + kc * 64 + k]
                         : score_w[(row - 48) * CC + kc * 64 + k];
    g_hw[idx] = __float2half(v);
}

// ---------------------------------------------------------------------------
// Conv 3x3, single-pass fp16, K-split x4 (R10 config — best measured).
// grid (128, 4, 4) = 2048 CTAs, 256 thr, 2 CTAs/SM.
// CTA tile M=128 x N=128, 18 chunks of 64 ic. 8 warps, warp tile 32x64.
// Stage = A16K + B16K = 32KB, 3 stages (96KB), depth-2 prefetch, single
// __syncthreads per chunk (ring refill into stage (i+2)%3).
// Partials stored fp16.
// ---------------------------------------------------------------------------
#define CSTG  32768
#define CDYN  (3*CSTG)

__device__ __forceinline__ void conv_load_chunk(unsigned sb, int ci, int s,
                                                int y, int oc0, int tid){
    const int tap = ci >> 3;
    const int ic0 = (ci & 7) << 6;
    const int dy = tap / 3 - 1, dx = tap % 3 - 1;
    const int yy = y + dy;
    const bool rowok = ((unsigned)yy < 128u);
    const unsigned stg = sb + s * CSTG;
    #pragma unroll
    for (int j = 0; j < 8; j++){
        int id = tid + j * 256;
        if (id < 1024){                       // A (16KB)
            int row = id >> 3, c = id & 7;
            unsigned dst = stg + SWZ(row * 128 + c * 16);
            int wx = row + dx;
            bool ok = rowok && ((unsigned)wx < 128u);
            const __half* src = g_xhi +
                (ok ? ((size_t)(yy * 128 + wx) * CC + ic0 + c * 8) : 0);
            cp16(dst, src, ok ? 16u : 0u);
        } else {                              // B (16KB)
            int idb = id - 1024;
            int row = idb >> 3, c = idb & 7;
            unsigned dst = stg + 16384 + SWZ(row * 128 + c * 16);
            cp16(dst, g_wh + (size_t)tap * (CC * CC)
                     + (size_t)(oc0 + row) * CC + ic0 + c * 8, 16u);
        }
    }
}

__global__ void __launch_bounds__(256, 2) conv_mma_kernel(){
    extern __shared__ __align__(1024) char dsm[];
    const unsigned sb = smem_u32(dsm);
    const int tid = threadIdx.x, lane = tid & 31, wid = tid >> 5;
    const int y = blockIdx.x, oc0 = blockIdx.y * 128, ks = blockIdx.z;
    const int cbase = ks * 18;
    const int m0 = (wid & 3) * 32, n0 = (wid >> 2) * 64;

    float acc[2][8][4];
    #pragma unroll
    for (int a = 0; a < 2; a++)
        #pragma unroll
        for (int b = 0; b < 8; b++)
            #pragma unroll
            for (int c = 0; c < 4; c++) acc[a][b][c] = 0.f;

    const int a_row = lane & 15;
    const int a_kad = (lane >> 4) << 4;
    const int b_row = ((lane >> 4) << 3) + (lane & 7);
    const int b_kad = ((lane >> 3) & 1) << 4;

    conv_load_chunk(sb, cbase + 0, 0, y, oc0, tid); CP_COMMIT();
    conv_load_chunk(sb, cbase + 1, 1, y, oc0, tid); CP_COMMIT();

    int s = 0;
    for (int i = 0; i < 18; i++){
        if (i <= 16) CP_WAIT(1);
        else         CP_WAIT(0);
        __syncthreads();

        const unsigned Ah = sb + s * CSTG;
        const unsigned Bh = Ah + 16384;

        #pragma unroll
        for (int k16 = 0; k16 < 4; k16++){
            const int koff = k16 * 32;
            unsigned ah[2][4];
            #pragma unroll
            for (int mt = 0; mt < 2; mt++)
                ldm4(ah[mt], Ah + SWZ((m0 + mt * 16 + a_row) * 128 + koff + a_kad));
            unsigned bh[4][4];
            #pragma unroll
            for (int bt = 0; bt < 4; bt++)
                ldm4(bh[bt], Bh + SWZ((n0 + bt * 16 + b_row) * 128 + koff + b_kad));
            #pragma unroll
            for (int mt = 0; mt < 2; mt++)
                #pragma unroll
                for (int bt = 0; bt < 4; bt++){
                    mma16816(acc[mt][2*bt],   ah[mt], &bh[bt][0]);
                    mma16816(acc[mt][2*bt+1], ah[mt], &bh[bt][2]);
                }
        }

        if (i + 2 < 18){
            conv_load_chunk(sb, cbase + i + 2, (i + 2) % 3, y, oc0, tid);
            CP_COMMIT();
        }
        s = (s == 2) ? 0 : s + 1;
    }

    // Store fp16 partials
    __half* pb = g_part[ks];
    const int er = lane >> 2;
    const int ec = (lane & 3) * 2;
    #pragma unroll
    for (int mt = 0; mt < 2; mt++){
        #pragma unroll
        for (int nt = 0; nt < 8; nt++){
            const int oc = oc0 + n0 + nt * 8 + ec;
            #pragma unroll
            for (int h = 0; h < 2; h++){
                const size_t p = (size_t)y * 128 + m0 + mt * 16 + er + h * 8;
                *(__half2*)&pb[p * CC + oc] =
                    __floats2half2_rn(acc[mt][nt][2*h+0], acc[mt][nt][2*h+1]);
            }
        }
    }
}

// ---------------------------------------------------------------------------
// Epilogue: sum 4 fp16 partials + bias + relu, split fp16 hi/lo
// ---------------------------------------------------------------------------
__global__ void __launch_bounds__(256) mid_epilogue_kernel(const float* __restrict__ bias){
    const size_t i4 = ((size_t)blockIdx.x * 256 + threadIdx.x) * 4;
    const int oc = (int)(i4 & 511);
    float4 b4 = *(const float4*)&bias[oc];
    float v[4] = {b4.x, b4.y, b4.z, b4.w};
    #pragma unroll
    for (int k = 0; k < 4; k++){
        uint2 raw = *(const uint2*)&g_part[k][i4];
        __half2 p01 = *reinterpret_cast<__half2*>(&raw.x);
        __half2 p23 = *reinterpret_cast<__half2*>(&raw.y);
        float2 f01 = __half22float2(p01);
        float2 f23 = __half22float2(p23);
        v[0] += f01.x; v[1] += f01.y; v[2] += f23.x; v[3] += f23.y;
    }
    #pragma unroll
    for (int k = 0; k < 4; k++) v[k] = fmaxf(v[k], 0.f);
    __half h0 = __float2half(v[0]), h1 = __float2half(v[1]);
    __half h2 = __float2half(v[2]), h3 = __float2half(v[3]);
    __half l0 = __float2half(v[0] - __half2float(h0));
    __half l1 = __float2half(v[1] - __half2float(h1));
    __half l2 = __float2half(v[2] - __half2float(h2));
    __half l3 = __float2half(v[3] - __half2float(h3));
    uint2 hp = make_uint2((unsigned)*(unsigned short*)&h0 | ((unsigned)*(unsigned short*)&h1 << 16),
                          (unsigned)*(unsigned short*)&h2 | ((unsigned)*(unsigned short*)&h3 << 16));
    uint2 lp = make_uint2((unsigned)*(unsigned short*)&l0 | ((unsigned)*(unsigned short*)&l1 << 16),
                          (unsigned)*(unsigned short*)&l2 | ((unsigned)*(unsigned short*)&l3 << 16));
    *(uint2*)&g_mhi[i4] = hp;
    *(uint2*)&g_mlo[i4] = lp;
}

// ---------------------------------------------------------------------------
// Head GEMM + fused roi decode. M=128/CTA (grid 128), N=72, K=512.
// 2-pass fp16 (mid hi/lo).
// ---------------------------------------------------------------------------
#define HB    73728
#define HASTG 32768
#define HDYN  (HB + 2*HASTG)

__device__ __forceinline__ void head_load_A(unsigned sb, int i, int s,
                                            int p0, int tid){
    const unsigned ast = sb + HB + s * HASTG;
    const int ic0 = i * 64;
    #pragma unroll
    for (int j = 0; j < 8; j++){
        int id = tid + j * 256;
        int part = id >> 10, rem = id & 1023;
        int row = rem >> 3, c = rem & 7;
        unsigned dst = ast + part * 16384 + SWZ(row * 128 + c * 16);
        const __half* base = part ? g_mlo : g_mhi;
        cp16(dst, base + (size_t)(p0 + row) * CC + ic0 + c * 8, 16u);
    }
}

__device__ __forceinline__ void emit_locroi(float* __restrict__ out,
                                            int p, int col, float v0, float v1){
    *(float2*)&out[LOC_OFF + (size_t)p * 48 + col] = make_float2(v0, v1);
    const int a = col >> 2;
    const float RAT[3] = {0.5f, 1.0f, 2.0f};
    const float SIZ[4] = {64.f, 128.f, 256.f, 512.f};
    float r = RAT[a >> 2], sz = SIZ[a & 3];
    float hr = sqrtf(r);
    float aw = rintf(0.5f * ((1.0f / hr) * sz));
    float ah = rintf(0.5f * (hr * sz));
    float gx = (float)((p >> 7) * 16);
    float gy = (float)((p & 127) * 16);
    float2 ro;
    if ((col & 3) == 0){
        ro = make_float2(v0 * aw + gx, v1 * ah + gy);
    } else {
        ro = make_float2(expf(v0) * aw, expf(v1) * ah);
    }
    *(float2*)&out[ROI_OFF + (size_t)p * 48 + col] = ro;
}

__global__ void __launch_bounds__(256, 1) head_mma_kernel(
        const float* __restrict__ loc_b, const float* __restrict__ score_b,
        float* __restrict__ out){
    extern __shared__ __align__(1024) char dsm[];
    const unsigned sb = smem_u32(dsm);
    const int tid = threadIdx.x, lane = tid & 31, wid = tid >> 5;
    const int p0 = blockIdx.x * 128;
    const int m0 = wid * 16;

    float acc[9][4];
    #pragma unroll
    for (int n = 0; n < 9; n++)
        #pragma unroll
        for (int c = 0; c < 4; c++) acc[n][c] = 0.f;

    #pragma unroll
    for (int j = 0; j < 18; j++){
        int id = tid + j * 256;
        int kc  = id / 576;
        int rem = id % 576;
        int row = rem >> 3, c = rem & 7;
        unsigned dst = sb + kc * 9216 + SWZ(row * 128 + c * 16);
        cp16(dst, g_hw + kc * 4608 + row * 64 + c * 8, 16u);
    }
    head_load_A(sb, 0, 0, p0, tid);
    CP_COMMIT();

    const int a_row = lane & 15;
    const int a_kad = (lane >> 4) << 4;
    const int b_row = lane & 7;
    const int b_kad = ((lane >> 3) & 1) << 4;

    for (int i = 0; i < 8; i++){
        const int s = i & 1;
        if (i < 7){
            head_load_A(sb, i + 1, (i + 1) & 1, p0, tid);
            CP_COMMIT();
            CP_WAIT(1);
        } else {
            CP_WAIT(0);
        }
        __syncthreads();

        const unsigned Ah = sb + HB + s * HASTG;
        const unsigned Al = Ah + 16384;
        const unsigned Bh = sb + i * 9216;

        #pragma unroll
        for (int k16 = 0; k16 < 4; k16++){
            const int koff = k16 * 32;
            unsigned ah[4], al[4];
            {
                unsigned off = SWZ((m0 + a_row) * 128 + koff + a_kad);
                ldm4(ah, Ah + off);
                ldm4(al, Al + off);
            }
            #pragma unroll
            for (int nt = 0; nt < 9; nt++){
                unsigned off = SWZ((nt * 8 + b_row) * 128 + koff + b_kad);
                unsigned bh2[2];
                ldm2(bh2, Bh + off);
                mma16816(acc[nt], ah, bh2);
                mma16816(acc[nt], al, bh2);
            }
        }
        __syncthreads();
    }

    const int er = lane >> 2;
    const int ec = (lane & 3) * 2;
    #pragma unroll
    for (int nt = 0; nt < 9; nt++){
        const int col = nt * 8 + ec;
        const int p1 = p0 + m0 + er;
        const int p2 = p1 + 8;
        if (col < 48){
            float2 b2 = *(const float2*)&loc_b[col];
            emit_locroi(out, p1, col, acc[nt][0] + b2.x, acc[nt][1] + b2.y);
            emit_locroi(out, p2, col, acc[nt][2] + b2.x, acc[nt][3] + b2.y);
        } else {
            const int cc2 = col - 48;
            float2 b2 = *(const float2*)&score_b[cc2];
            *(float2*)&out[CLS_OFF + (size_t)p1 * 24 + cc2] =
                make_float2(acc[nt][0] + b2.x, acc[nt][1] + b2.y);
            *(float2*)&out[CLS_OFF + (size_t)p2 * 24 + cc2] =
                make_float2(acc[nt][2] + b2.x, acc[nt][3] + b2.y);
        }
    }
}

// ---------------------------------------------------------------------------
extern "C" void kernel_launch(void* const* d_in, const int* in_sizes, int n_in,
                              void* d_out, int out_size){
    const float* x       = (const float*)d_in[0];
    const float* conv1_w = (const float*)d_in[1];
    const float* conv1_b = (const float*)d_in[2];
    const float* score_w = (const float*)d_in[3];
    const float* score_b = (const float*)d_in[4];
    const float* loc_w   = (const float*)d_in[5];
    const float* loc_b   = (const float*)d_in[6];
    float* out = (float*)d_out;

    cudaFuncSetAttribute(conv_mma_kernel,
        cudaFuncAttributeMaxDynamicSharedMemorySize, CDYN);
    cudaFuncSetAttribute(head_mma_kernel,
        cudaFuncAttributeMaxDynamicSharedMemorySize, HDYN);

    prep_x_kernel<<<dim3(HWSZ / 32, CC / 32), dim3(32, 8)>>>(x);
    prep_w_kernel<<<512, 256>>>(conv1_w);
    prep_hw_kernel<<<(8 * 72 * 64 + 255) / 256, 256>>>(loc_w, score_w);

    conv_mma_kernel<<<dim3(128, 4, 4), 256, CDYN>>>();

    mid_epilogue_kernel<<<(HWSZ * CC / 4) / 256, 256>>>(conv1_b);

    head_mma_kernel<<<128, 256, HDYN>>>(loc_b, score_b, out);
}